// round 3
// baseline (speedup 1.0000x reference)
#include <cuda_runtime.h>
#include <cuda_bf16.h>
#include <cstdint>

#define BB 32
#define CC 80
#define HH 128
#define WW 128
#define HWSZ (HH * WW)      // 16384
#define KK 100
#define CAP 32768           // candidate slots per batch
#define NBINS 1024
#define BUFCAP 4096         // hard bound on 3x3 local maxima w/ distinct values

// Scratch (static device memory: allocation-free per harness rules)
__device__ unsigned int g_cnt[BB];      // zero at module load; stage2 resets
__device__ uint2 g_cand[BB * CAP];      // 8 MB

// ---------------------------------------------------------------------------
// Load one row (float4 per lane), compute horizontal 3-max per component.
// Warp lanes = 32 consecutive float4 column-groups of the same row.
__device__ __forceinline__ void ldrow(const float4* __restrict__ fp4, int y, int cg,
                                      float4& f4, float4& hm) {
    const float NEG = -1e30f;
    f4 = fp4[y * 32 + cg];
    float left  = __shfl_up_sync(0xffffffffu, f4.w, 1);
    float right = __shfl_down_sync(0xffffffffu, f4.x, 1);
    if (cg == 0)  left  = NEG;
    if (cg == 31) right = NEG;
    hm.x = fmaxf(fmaxf(left, f4.x), f4.y);
    hm.y = fmaxf(fmaxf(f4.x, f4.y), f4.z);
    hm.z = fmaxf(fmaxf(f4.y, f4.z), f4.w);
    hm.w = fmaxf(fmaxf(f4.z, f4.w), right);
}

__device__ __forceinline__ int val_bin(float v) {
    int bin = (int)(v * (float)NBINS);
    return max(0, min(NBINS - 1, bin));
}

// ---------------------------------------------------------------------------
// One block per (b, c) plane. 512 threads: 32 col-groups x 16 row-segments(8 rows).
__global__ __launch_bounds__(512) void k_stage1(const float* __restrict__ fmap) {
    __shared__ int hist[NBINS];
    __shared__ uint2 sbuf[BUFCAP];
    __shared__ int s_n;
    __shared__ int s_tbin;
    __shared__ unsigned s_cnt, s_off, s_base;

    const int plane = blockIdx.x;
    const int b = plane / CC;
    const int c = plane % CC;
    const float4* __restrict__ fp4 =
        (const float4*)(fmap + (size_t)plane * HWSZ);

    const int t = threadIdx.x;
    for (int i = t; i < NBINS; i += 512) hist[i] = 0;
    if (t == 0) { s_n = 0; s_cnt = 0u; s_off = 0u; s_tbin = 0; }
    __syncthreads();

    const int cg = t & 31;            // column group (4 consecutive x)
    const int y0 = (t >> 5) * 8;      // first row of this thread's segment
    const float NEG = -1e30f;

    float4 fcur, fnext;
    float4 hA, hB, hC;                // hmax of rows y-1, y, y+1

    if (y0 == 0) {
        hA = make_float4(NEG, NEG, NEG, NEG);
    } else {
        float4 d;
        ldrow(fp4, y0 - 1, cg, d, hA);
    }
    ldrow(fp4, y0, cg, fcur, hB);
    ldrow(fp4, y0 + 1, cg, fnext, hC);

#pragma unroll
    for (int r = 0; r < 8; r++) {
        const int y = y0 + r;
        float4 fnn, hD;
        if (r < 7) {                          // prefetch row y+2 early
            if (y + 2 <= HH - 1) {
                ldrow(fp4, y + 2, cg, fnn, hD);
            } else {
                hD = make_float4(NEG, NEG, NEG, NEG);
                fnn = fnext;
            }
        }
        float4 vm;
        vm.x = fmaxf(fmaxf(hA.x, hB.x), hC.x);
        vm.y = fmaxf(fmaxf(hA.y, hB.y), hC.y);
        vm.z = fmaxf(fmaxf(hA.z, hB.z), hC.z);
        vm.w = fmaxf(fmaxf(hA.w, hB.w), hC.w);

        const float va[4] = {fcur.x, fcur.y, fcur.z, fcur.w};
        const float vb[4] = {vm.x, vm.y, vm.z, vm.w};
#pragma unroll
        for (int q = 0; q < 4; q++) {
            if (va[q] >= vb[q]) {             // 3x3 local maximum (== window max)
                atomicAdd(&hist[val_bin(va[q])], 1);
                int idx = atomicAdd(&s_n, 1);
                uint2 e = make_uint2(__float_as_uint(va[q]),
                                     (unsigned)c * HWSZ + (unsigned)(y * WW + cg * 4 + q));
                if (idx < BUFCAP) {
                    sbuf[idx] = e;
                } else {                      // overflow: direct append (superset-safe)
                    unsigned g = atomicAdd(&g_cnt[b], 1u);
                    if (g < CAP) g_cand[(size_t)b * CAP + g] = e;
                }
            }
        }
        hA = hB; hB = hC;
        if (r < 7) { hC = hD; fcur = fnext; fnext = fnn; }
    }
    __syncthreads();

    // Warp 0: suffix-scan 1024 bins, find threshold bin keeping >= min(K, total).
    if (t < 32) {
        const int base = t * 32;
        int s = 0;
#pragma unroll
        for (int j = 0; j < 32; j++) s += hist[base + j];
        int suf = s;                           // inclusive suffix across lanes
#pragma unroll
        for (int off = 1; off < 32; off <<= 1) {
            int v = __shfl_down_sync(0xffffffffu, suf, off);
            if (t + off < 32) suf += v;
        }
        const int total = __shfl_sync(0xffffffffu, suf, 0);
        const int need = min(KK, total);
        int sufN = __shfl_down_sync(0xffffffffu, suf, 1);
        if (t == 31) sufN = 0;
        if (need > 0 && suf >= need && sufN < need) {
            int acc = sufN;
            int tb = base;
            for (int j = 31; j >= 0; j--) {
                acc += hist[base + j];
                if (acc >= need) { tb = base + j; break; }
            }
            s_tbin = tb;
        }
    }
    __syncthreads();

    // Filter staged candidates against threshold; block-aggregated append.
    const int tbin = s_tbin;
    const int n = min(s_n, BUFCAP);
    uint2 tmp[8];                              // n<=4096, stride 512 -> <=8 each
    int mycnt = 0;
    for (int i = t; i < n; i += 512) {
        uint2 cv = sbuf[i];
        if (val_bin(__uint_as_float(cv.x)) >= tbin) tmp[mycnt++] = cv;
    }
    if (mycnt) atomicAdd(&s_cnt, (unsigned)mycnt);
    __syncthreads();
    if (t == 0) s_base = atomicAdd(&g_cnt[b], s_cnt);
    __syncthreads();
    if (mycnt) {
        unsigned off = atomicAdd(&s_off, (unsigned)mycnt);
        unsigned g0 = s_base + off;
#pragma unroll
        for (int j = 0; j < 8; j++) {
            if (j < mycnt) {
                unsigned g = g0 + j;
                if (g < CAP) g_cand[(size_t)b * CAP + g] = tmp[j];
            }
        }
    }
}

// ---------------------------------------------------------------------------
// One block per batch: radix-select exact 100th value, collect >= T, bitonic
// sort 1024 keys, gather wh/reg, write bboxes | scores | clses. Resets g_cnt.
__global__ __launch_bounds__(512) void k_stage2(const float* __restrict__ wh,
                                                const float* __restrict__ reg,
                                                float* __restrict__ out) {
    __shared__ int whist[16][256];              // warp-private histograms
    __shared__ int hist2[256];
    __shared__ unsigned long long keys[1024];
    __shared__ int s_byte, s_above, s_wcnt;

    const int b = blockIdx.x;
    const int t = threadIdx.x;
    const int w = t >> 5;
    const int M = min((int)g_cnt[b], CAP);
    const uint2* __restrict__ cand = g_cand + (size_t)b * CAP;

    unsigned T = 0u;
    if (M > KK) {
        unsigned prefix = 0u, prefmask = 0u;
        int k = KK;
        for (int p = 3; p >= 0; p--) {
            for (int i = t; i < 16 * 256; i += 512) ((int*)whist)[i] = 0;
            __syncthreads();
            const int sh = p * 8;
            for (int i = t; i < M; i += 512) {
                unsigned v = cand[i].x;
                if ((v & prefmask) == prefix)
                    atomicAdd(&whist[w][(v >> sh) & 255], 1);
            }
            __syncthreads();
            if (t < 256) {
                int s = 0;
#pragma unroll
                for (int j = 0; j < 16; j++) s += whist[j][t];
                hist2[t] = s;
            }
            __syncthreads();
            // Warp 0: suffix-scan 256 bins, find crossing byte.
            if (t < 32) {
                const int base = t * 8;
                int s = 0;
#pragma unroll
                for (int j = 0; j < 8; j++) s += hist2[base + j];
                int suf = s;
#pragma unroll
                for (int off = 1; off < 32; off <<= 1) {
                    int v = __shfl_down_sync(0xffffffffu, suf, off);
                    if (t + off < 32) suf += v;
                }
                int sufN = __shfl_down_sync(0xffffffffu, suf, 1);
                if (t == 31) sufN = 0;
                if (suf >= k && sufN < k) {
                    int acc = sufN;
                    for (int j = 7; j >= 0; j--) {
                        acc += hist2[base + j];
                        if (acc >= k) {
                            s_byte = base + j;
                            s_above = acc - hist2[base + j];
                            break;
                        }
                    }
                }
            }
            __syncthreads();
            prefix |= ((unsigned)s_byte) << sh;
            prefmask |= 0xFFu << sh;
            k -= s_above;
            __syncthreads();
        }
        T = prefix;   // exact value bits of the 100th-largest candidate
    }

    if (t == 0) s_wcnt = 0;
    for (int i = t; i < 1024; i += 512) keys[i] = 0ull;
    __syncthreads();
    for (int i = t; i < M; i += 512) {
        uint2 cv = cand[i];
        if (cv.x >= T) {
            int s = atomicAdd(&s_wcnt, 1);
            if (s < 1024)
                keys[s] = ((unsigned long long)cv.x << 32) |
                          (unsigned long long)(0xFFFFFFFFu - cv.y);
        }
    }
    __syncthreads();

    // bitonic sort ascending; top-100 end up at indices 1023..924
    for (int kk2 = 2; kk2 <= 1024; kk2 <<= 1) {
        for (int j = kk2 >> 1; j > 0; j >>= 1) {
            for (int i = t; i < 1024; i += 512) {
                int ixj = i ^ j;
                if (ixj > i) {
                    unsigned long long a = keys[i], cc2 = keys[ixj];
                    bool up = ((i & kk2) == 0);
                    if ((a > cc2) == up) { keys[i] = cc2; keys[ixj] = a; }
                }
            }
            __syncthreads();
        }
    }

    const float* __restrict__ whb = wh + (size_t)b * 2 * HWSZ;
    const float* __restrict__ regb = reg + (size_t)b * 2 * HWSZ;
    if (t < KK) {
        const int r = t;
        unsigned long long key = keys[1023 - r];
        float val = __uint_as_float((unsigned)(key >> 32));
        unsigned pidx = 0xFFFFFFFFu - (unsigned)(key & 0xFFFFFFFFull);
        int cls = (int)(pidx >> 14);
        int pos = (int)(pidx & (HWSZ - 1));
        float yy = (float)(pos >> 7);
        float xx = (float)(pos & (WW - 1));
        float rx = regb[pos];
        float ry = regb[HWSZ + pos];
        float bw = whb[pos];
        float bh = whb[HWSZ + pos];
        float fx = xx + rx, fy = yy + ry;
        float hw2 = bw * 0.5f, hh2 = bh * 0.5f;
        float* bo = out + (size_t)(b * KK + r) * 4;
        bo[0] = fx - hw2;
        bo[1] = fy - hh2;
        bo[2] = fx + hw2;
        bo[3] = fy + hh2;
        out[BB * KK * 4 + b * KK + r] = val;                  // scores
        out[BB * KK * 4 + BB * KK + b * KK + r] = (float)cls; // classes
    }

    if (t == 0) g_cnt[b] = 0u;   // reset for next graph replay
}

// ---------------------------------------------------------------------------
extern "C" void kernel_launch(void* const* d_in, const int* in_sizes, int n_in,
                              void* d_out, int out_size) {
    const float* fmap = (const float*)d_in[0];
    const float* wh   = (const float*)d_in[1];
    const float* reg  = (const float*)d_in[2];
    float* out = (float*)d_out;

    k_stage1<<<BB * CC, 512>>>(fmap);
    k_stage2<<<BB, 512>>>(wh, reg, out);
}